// round 7
// baseline (speedup 1.0000x reference)
#include <cuda_runtime.h>
#include <cstdint>
#include <cstddef>

// Problem constants
#define BB   16
#define CC   64
#define NN   2048
#define KK   20
#define OUTC 64

// ---------------- scratch (no allocations allowed) ----------------
__device__ __align__(16) float g_xt[BB * NN * CC];     // x transposed: [b][n][c]
__device__ float g_sq[BB * NN];                        // squared norms (bit-exact vs ref)
__device__ int   g_idx[BB * NN * KK];                  // knn indices, ascending dist
__device__ __align__(16) float g_wp[21 * CC * OUTC];   // slot-major weights [slot][c][o]
__device__ float g_scale[OUTC];
__device__ float g_shift[OUTC];

// ---------------- prep: transpose x -> xt ----------------
__global__ void prep_xt_kernel(const float* __restrict__ x) {
    __shared__ float sm[64][129];
    int b = blockIdx.y, n0 = blockIdx.x * 128, t = threadIdx.x;
    const float* xb = x + (size_t)b * CC * NN;
#pragma unroll
    for (int c = 0; c < 64; c++)
        sm[c][t] = xb[(size_t)c * NN + n0 + t];
    __syncthreads();
    float* xtb = g_xt + ((size_t)b * NN + n0) * 64;
#pragma unroll 4
    for (int i = 0; i < 64; i++) {
        int flat = i * 128 + t;
        int c = flat & 63, p = flat >> 6;
        xtb[(size_t)p * 64 + c] = sm[c][p];
    }
}

// ---------------- sq: XLA:CPU + LLVM LoopVectorizer replica ----------------
// square+reduce loop vectorized for AArch64: VF=4 (NEON), IC=2 -> 8 lanes.
//   lane l accumulates elements c == l (mod 8), ascending, each product
//   rounded separately (fmul then fadd, NO contract/fma).
// Epilogue: interleaved parts combined by vector fadd (V0+V1), then
// vector.reduce.fadd lowered via AArch64 faddp pairs: (t0+t1)+(t2+t3).
__global__ __launch_bounds__(256) void sq_kernel() {
    int p = blockIdx.x * 256 + threadIdx.x;    // point index
    const float4* z = (const float4*)(g_xt + (size_t)p * 64);
    float a[8];
#pragma unroll
    for (int l = 0; l < 8; l++) a[l] = 0.f;
#pragma unroll
    for (int i = 0; i < 8; i++) {
        float4 v0 = z[2 * i];
        float4 v1 = z[2 * i + 1];
        a[0] = __fadd_rn(a[0], __fmul_rn(v0.x, v0.x));
        a[1] = __fadd_rn(a[1], __fmul_rn(v0.y, v0.y));
        a[2] = __fadd_rn(a[2], __fmul_rn(v0.z, v0.z));
        a[3] = __fadd_rn(a[3], __fmul_rn(v0.w, v0.w));
        a[4] = __fadd_rn(a[4], __fmul_rn(v1.x, v1.x));
        a[5] = __fadd_rn(a[5], __fmul_rn(v1.y, v1.y));
        a[6] = __fadd_rn(a[6], __fmul_rn(v1.z, v1.z));
        a[7] = __fadd_rn(a[7], __fmul_rn(v1.w, v1.w));
    }
    float t0 = __fadd_rn(a[0], a[4]);
    float t1 = __fadd_rn(a[1], a[5]);
    float t2 = __fadd_rn(a[2], a[6]);
    float t3 = __fadd_rn(a[3], a[7]);
    g_sq[p] = __fadd_rn(__fadd_rn(t0, t1), __fadd_rn(t2, t3));
}

// ---------------- prep: reorganize weights ----------------
// slot 0 : w1sum[c][o] = sum_j (w[o][c][j] - w[o][C+c][j])   (applied to central point)
// slot 1+j : w[o][C+c][j]                                    (applied to neighbor j)
__global__ void prep_w_kernel(const float* __restrict__ w) {
    int c = blockIdx.x;   // 0..63
    int o = threadIdx.x;  // 0..63
    const float* w1 = w + ((size_t)o * 128 + c) * 20;
    const float* w2 = w + ((size_t)o * 128 + 64 + c) * 20;
    float s = 0.f;
#pragma unroll
    for (int j = 0; j < 20; j++) {
        float a = w1[j], d = w2[j];
        s += a - d;
        g_wp[(size_t)(1 + j) * 4096 + c * 64 + o] = d;
    }
    g_wp[c * 64 + o] = s;
}

// ---------------- knn: fused distance + top-20 selection ----------------
// Distance replicates the reference bit-exactly:
//   dot   = sequential ascending single-accumulator fma (Eigen gebp NEON vfma
//           k-loop semantics)
//   dist  = fma(-2, dot, round(sq_i + sq_j))   (== (sq_i+sq_j) - 2*dot, one
//           rounding, since 2*dot is exact)
// Top-20 kept UNSORTED in registers with tracked lexicographic (dist, idx) max.
__global__ __launch_bounds__(128) void knn_kernel() {
    __shared__ __align__(16) float cs[32 * 64];
    __shared__ float csq[32];
    int b = blockIdx.y;
    int q = blockIdx.x * 128 + threadIdx.x;
    const float* xb = g_xt + (size_t)b * NN * 64;

    float qr[64];
    {
        const float4* qp = (const float4*)(xb + (size_t)q * 64);
#pragma unroll
        for (int k = 0; k < 16; k++) {
            float4 v = qp[k];
            qr[4 * k] = v.x; qr[4 * k + 1] = v.y; qr[4 * k + 2] = v.z; qr[4 * k + 3] = v.w;
        }
    }
    float sqq = g_sq[b * NN + q];

    const float INF = __int_as_float(0x7f800000);
    float kd[20]; int ki[20];
#pragma unroll
    for (int k = 0; k < 20; k++) { kd[k] = INF; ki[k] = 0x7fffffff; }
    float wd = INF; int wi = 0x7fffffff; int ws = 0;

    for (int t0 = 0; t0 < NN; t0 += 32) {
        __syncthreads();
        {
            const float4* src = (const float4*)(xb + (size_t)t0 * 64);
            float4* dst = (float4*)cs;
#pragma unroll
            for (int k = 0; k < 4; k++) dst[threadIdx.x + 128 * k] = src[threadIdx.x + 128 * k];
            if (threadIdx.x < 32) csq[threadIdx.x] = g_sq[b * NN + t0 + threadIdx.x];
        }
        __syncthreads();
#pragma unroll 1
        for (int cc = 0; cc < 32; cc += 2) {
            // two interleaved sequential fma chains for ILP
            const float* cva = cs + cc * 64;
            const float* cvb = cs + (cc + 1) * 64;
            float da = 0.f, db = 0.f;
#pragma unroll
            for (int c = 0; c < 64; c++) {
                da = __fmaf_rn(qr[c], cva[c], da);
                db = __fmaf_rn(qr[c], cvb[c], db);
            }
            float ta = __fadd_rn(sqq, csq[cc]);
            float tb = __fadd_rn(sqq, csq[cc + 1]);
            float dsta = __fmaf_rn(-2.f, da, ta);
            float dstb = __fmaf_rn(-2.f, db, tb);
#pragma unroll
            for (int h = 0; h < 2; h++) {
                float dst = h ? dstb : dsta;
                int ci = t0 + cc + h;
                bool take = (ci != q) && (dst < wd || (dst == wd && ci < wi));
                if (take) {
#pragma unroll
                    for (int k = 0; k < 20; k++) if (k == ws) { kd[k] = dst; ki[k] = ci; }
                    wd = kd[0]; wi = ki[0]; ws = 0;
#pragma unroll
                    for (int k = 1; k < 20; k++) {
                        bool g = (kd[k] > wd) || (kd[k] == wd && ki[k] > wi);
                        if (g) { wd = kd[k]; wi = ki[k]; ws = k; }
                    }
                }
            }
        }
    }

    // output ascending (dist, idx) — matches jax top_k ordering with ties by index
    int* outp = g_idx + ((size_t)b * NN + q) * 20;
#pragma unroll 1
    for (int s = 0; s < 20; s++) {
        float bd = kd[0]; int bi = ki[0]; int bs = 0;
#pragma unroll
        for (int k = 1; k < 20; k++) {
            bool l = (kd[k] < bd) || (kd[k] == bd && ki[k] < bi);
            if (l) { bd = kd[k]; bi = ki[k]; bs = k; }
        }
        outp[s] = bi;
#pragma unroll
        for (int k = 0; k < 20; k++) if (k == bs) { kd[k] = INF; ki[k] = 0x7fffffff; }
    }
}

// ---------------- edgeconv: gather + slotted GEMM ----------------
// Block: 64 points x 64 outputs. Thread: 2 points x 8 outputs (16 acc regs).
__global__ __launch_bounds__(256) void edgeconv_kernel(const float* __restrict__ bias,
                                                       float* __restrict__ out) {
    __shared__ __align__(16) float wsm[64 * 64];
    __shared__ __align__(16) float nb[64 * 66];   // pad 66 -> conflict-free strided reads
    __shared__ int idxs[64 * 20];

    int b = blockIdx.y;
    int n0 = blockIdx.x * 64;
    int tid = threadIdx.x;
    int og = tid & 7;        // output group: o = og*8 .. og*8+7
    int pg = tid >> 3;       // 0..31
    int p0 = pg * 2, p1 = pg * 2 + 1;
    const float* xb = g_xt + (size_t)b * NN * 64;

    for (int i = tid; i < 64 * 20; i += 256)
        idxs[i] = g_idx[((size_t)b * NN + n0 + (i / 20)) * 20 + (i % 20)];

    float4 a0a = {0, 0, 0, 0}, a0b = {0, 0, 0, 0};
    float4 a1a = {0, 0, 0, 0}, a1b = {0, 0, 0, 0};

    for (int slot = 0; slot < 21; slot++) {
        __syncthreads();
#pragma unroll
        for (int k = 0; k < 4; k++)
            ((float4*)wsm)[tid + 256 * k] =
                ((const float4*)(g_wp + (size_t)slot * 4096))[tid + 256 * k];
        {
            int pt = tid >> 2, tsub = tid & 3;
            int srcn = (slot == 0) ? (n0 + pt) : idxs[pt * 20 + slot - 1];
            const float2* s2 = (const float2*)(xb + (size_t)srcn * 64) + tsub * 8;
            float2* d2 = (float2*)(nb + pt * 66) + tsub * 8;
#pragma unroll
            for (int k = 0; k < 8; k++) d2[k] = s2[k];
        }
        __syncthreads();
#pragma unroll 2
        for (int c = 0; c < 64; c++) {
            const float4* wr = (const float4*)(wsm + c * 64);
            float4 w0 = wr[og * 2];
            float4 w1 = wr[og * 2 + 1];
            float v0 = nb[p0 * 66 + c];
            float v1 = nb[p1 * 66 + c];
            a0a.x = fmaf(v0, w0.x, a0a.x); a0a.y = fmaf(v0, w0.y, a0a.y);
            a0a.z = fmaf(v0, w0.z, a0a.z); a0a.w = fmaf(v0, w0.w, a0a.w);
            a0b.x = fmaf(v0, w1.x, a0b.x); a0b.y = fmaf(v0, w1.y, a0b.y);
            a0b.z = fmaf(v0, w1.z, a0b.z); a0b.w = fmaf(v0, w1.w, a0b.w);
            a1a.x = fmaf(v1, w0.x, a1a.x); a1a.y = fmaf(v1, w0.y, a1a.y);
            a1a.z = fmaf(v1, w0.z, a1a.z); a1a.w = fmaf(v1, w0.w, a1a.w);
            a1b.x = fmaf(v1, w1.x, a1b.x); a1b.y = fmaf(v1, w1.y, a1b.y);
            a1b.z = fmaf(v1, w1.z, a1b.z); a1b.w = fmaf(v1, w1.w, a1b.w);
        }
    }

    float4 bb0 = ((const float4*)bias)[og * 2];
    float4 bb1 = ((const float4*)bias)[og * 2 + 1];
    a0a.x += bb0.x; a0a.y += bb0.y; a0a.z += bb0.z; a0a.w += bb0.w;
    a0b.x += bb1.x; a0b.y += bb1.y; a0b.z += bb1.z; a0b.w += bb1.w;
    a1a.x += bb0.x; a1a.y += bb0.y; a1a.z += bb0.z; a1a.w += bb0.w;
    a1b.x += bb1.x; a1b.y += bb1.y; a1b.z += bb1.z; a1b.w += bb1.w;

    float* ob = out + (size_t)b * OUTC * NN;
    int o0 = og * 8;
    ob[(size_t)(o0 + 0) * NN + n0 + p0] = a0a.x;
    ob[(size_t)(o0 + 1) * NN + n0 + p0] = a0a.y;
    ob[(size_t)(o0 + 2) * NN + n0 + p0] = a0a.z;
    ob[(size_t)(o0 + 3) * NN + n0 + p0] = a0a.w;
    ob[(size_t)(o0 + 4) * NN + n0 + p0] = a0b.x;
    ob[(size_t)(o0 + 5) * NN + n0 + p0] = a0b.y;
    ob[(size_t)(o0 + 6) * NN + n0 + p0] = a0b.z;
    ob[(size_t)(o0 + 7) * NN + n0 + p0] = a0b.w;
    ob[(size_t)(o0 + 0) * NN + n0 + p1] = a1a.x;
    ob[(size_t)(o0 + 1) * NN + n0 + p1] = a1a.y;
    ob[(size_t)(o0 + 2) * NN + n0 + p1] = a1a.z;
    ob[(size_t)(o0 + 3) * NN + n0 + p1] = a1a.w;
    ob[(size_t)(o0 + 4) * NN + n0 + p1] = a1b.x;
    ob[(size_t)(o0 + 5) * NN + n0 + p1] = a1b.y;
    ob[(size_t)(o0 + 6) * NN + n0 + p1] = a1b.z;
    ob[(size_t)(o0 + 7) * NN + n0 + p1] = a1b.w;
}

// ---------------- batchnorm stats (one block per channel) ----------------
__global__ void bn_stats_kernel(const float* __restrict__ y,
                                const float* __restrict__ gamma,
                                const float* __restrict__ beta) {
    int o = blockIdx.x, tid = threadIdx.x;
    float s = 0.f, ss = 0.f;
    for (int b = 0; b < BB; b++) {
        const float* p = y + ((size_t)b * OUTC + o) * NN;
        for (int i = tid; i < NN; i += 256) {
            float v = p[i];
            s += v;
            ss = fmaf(v, v, ss);
        }
    }
#pragma unroll
    for (int off = 16; off; off >>= 1) {
        s  += __shfl_down_sync(0xffffffffu, s, off);
        ss += __shfl_down_sync(0xffffffffu, ss, off);
    }
    __shared__ float shs[8], shss[8];
    int w = tid >> 5;
    if ((tid & 31) == 0) { shs[w] = s; shss[w] = ss; }
    __syncthreads();
    if (tid == 0) {
        s = 0.f; ss = 0.f;
#pragma unroll
        for (int k = 0; k < 8; k++) { s += shs[k]; ss += shss[k]; }
        float inv = 1.f / 32768.f;
        float mean = s * inv;
        float var = fmaf(ss, inv, -mean * mean);
        float r = rsqrtf(var + 1e-5f);
        float sc = gamma[o] * r;
        g_scale[o] = sc;
        g_shift[o] = beta[o] - mean * sc;
    }
}

// ---------------- normalize + leaky relu ----------------
__global__ void bn_apply_kernel(float* __restrict__ y) {
    int i = blockIdx.x * 256 + threadIdx.x;
    int o = (i >> 11) & 63;
    float v = fmaf(y[i], g_scale[o], g_shift[o]);
    y[i] = v >= 0.f ? v : 0.2f * v;
}

// ---------------- launch ----------------
extern "C" void kernel_launch(void* const* d_in, const int* in_sizes, int n_in,
                              void* d_out, int out_size) {
    const float* x     = (const float*)d_in[0];  // (16, 64, 2048)
    const float* w     = (const float*)d_in[1];  // (64, 128, 20)
    const float* bias  = (const float*)d_in[2];  // (64,)
    const float* gamma = (const float*)d_in[3];  // (64,)
    const float* beta  = (const float*)d_in[4];  // (64,)
    float* out = (float*)d_out;                  // (16, 64, 2048)

    prep_xt_kernel<<<dim3(NN / 128, BB), 128>>>(x);
    sq_kernel<<<(BB * NN) / 256, 256>>>();
    prep_w_kernel<<<64, 64>>>(w);
    knn_kernel<<<dim3(NN / 128, BB), 128>>>();
    edgeconv_kernel<<<dim3(NN / 64, BB), 256>>>(bias, out);
    bn_stats_kernel<<<OUTC, 256>>>(out, gamma, beta);
    bn_apply_kernel<<<(BB * OUTC * NN) / 256, 256>>>(out);
}